// round 4
// baseline (speedup 1.0000x reference)
#include <cuda_runtime.h>

#define N_NODES 50000
#define F0 96
#define F1 128
#define F2 64

// ---- persistent scratch (alloc-free per harness rules) ----
__device__ float g_agg1[N_NODES * F0];   // mean-agg input features, layer 1
__device__ float g_h   [N_NODES * F1];   // hidden activations
__device__ float g_agg2[N_NODES * F1];   // mean-agg hidden, layer 2
__device__ float g_deg [N_NODES];        // in-degree (shared across layers)
__device__ float g_w1l[F1 * F0];
__device__ float g_w1r[F1 * F0];
__device__ float g_w2l[F2 * F1];
__device__ float g_w2r[F2 * F1];
__device__ int   g_is64;                 // edge_index dtype flag

// ---------------------------------------------------------------------------
// Detect whether edge_index is int64 or int32 (JAX canonicalizes int64->int32
// unless x64 is enabled). If data is int32, interpreting as int64 yields
// values >= N_NODES with overwhelming probability.
// ---------------------------------------------------------------------------
__global__ void detect_kernel(const void* __restrict__ ei) {
    if (threadIdx.x == 0 && blockIdx.x == 0) {
        const long long* p = (const long long*)ei;
        int ok = 1;
        #pragma unroll
        for (int i = 0; i < 8; i++) {
            long long v = p[i];
            if (v < 0 || v >= N_NODES) ok = 0;
        }
        g_is64 = ok;
    }
}

// ---------------------------------------------------------------------------
// Zero the accumulation buffers (d_out is poisoned; scratch persists across
// graph replays, so must be re-zeroed every launch).
// ---------------------------------------------------------------------------
__global__ void zero_kernel() {
    const int n1 = N_NODES * F0;
    const int n2 = N_NODES * F1;
    const int total = n1 + n2 + N_NODES;
    for (int i = blockIdx.x * blockDim.x + threadIdx.x; i < total;
         i += gridDim.x * blockDim.x) {
        if (i < n1)            g_agg1[i] = 0.0f;
        else if (i < n1 + n2)  g_agg2[i - n1] = 0.0f;
        else                   g_deg [i - n1 - n2] = 0.0f;
    }
}

// ---------------------------------------------------------------------------
// Presign weights: sign(w) in {-1, 0, +1} (matches jnp.sign forward).
// ---------------------------------------------------------------------------
__global__ void prep_w(const float* __restrict__ w1l, const float* __restrict__ w1r,
                       const float* __restrict__ w2l, const float* __restrict__ w2r) {
    const int s12 = F1 * F0;          // 12288
    const int s34 = F2 * F1;          // 8192
    const int total = 2 * s12 + 2 * s34;
    for (int i = blockIdx.x * blockDim.x + threadIdx.x; i < total;
         i += gridDim.x * blockDim.x) {
        float w;
        float* dstp;
        if (i < s12)                { w = w1l[i];               dstp = &g_w1l[i]; }
        else if (i < 2 * s12)       { w = w1r[i - s12];         dstp = &g_w1r[i - s12]; }
        else if (i < 2 * s12 + s34) { w = w2l[i - 2 * s12];     dstp = &g_w2l[i - 2 * s12]; }
        else                        { w = w2r[i - 2 * s12 - s34]; dstp = &g_w2r[i - 2 * s12 - s34]; }
        *dstp = (w > 0.0f) ? 1.0f : ((w < 0.0f) ? -1.0f : 0.0f);
    }
}

// ---------------------------------------------------------------------------
// Edge scatter: one warp per edge. Gather src row (coalesced within warp),
// atomicAdd into dst row. Layer 1 also accumulates degree.
// ---------------------------------------------------------------------------
template <int F, bool L1>
__global__ void scatter_kernel(const float* __restrict__ xin,
                               const void* __restrict__ ei, int E) {
    int e = blockIdx.x * (blockDim.x >> 5) + (threadIdx.x >> 5);
    if (e >= E) return;
    int lane = threadIdx.x & 31;

    int s, d;
    if (g_is64) {
        const long long* p = (const long long*)ei;
        s = (int)__ldg(&p[e]);
        d = (int)__ldg(&p[E + e]);
    } else {
        const int* p = (const int*)ei;
        s = __ldg(&p[e]);
        d = __ldg(&p[E + e]);
    }

    const float* src_row = (L1 ? xin : (const float*)g_h) + (size_t)s * F;
    float*       dst_row = (L1 ? g_agg1 : g_agg2)          + (size_t)d * F;

    #pragma unroll
    for (int f = lane; f < F; f += 32)
        atomicAdd(dst_row + f, __ldg(src_row + f));

    if (L1 && lane == 0)
        atomicAdd(&g_deg[d], 1.0f);
}

// ---------------------------------------------------------------------------
// Fused SAGE linear: out[i] = (agg[i]/max(deg,1)) @ sgn(Wl)^T + b + xin[i] @ sgn(Wr)^T
// Block = OUT threads (one output column each), TN nodes staged in shared.
// Shared reads are warp-broadcast (all lanes same address), conflict-free.
// ---------------------------------------------------------------------------
template <bool L1Flag, int IN, int OUT, int TN, bool RELU>
__global__ void linear_kernel(const float* __restrict__ xparam,
                              const float* __restrict__ bias,
                              float* __restrict__ outparam) {
    const float* agg = L1Flag ? g_agg1 : g_agg2;
    const float* xin = L1Flag ? xparam : (const float*)g_h;
    const float* wl  = L1Flag ? g_w1l  : g_w2l;
    const float* wr  = L1Flag ? g_w1r  : g_w2r;
    float*       out = L1Flag ? g_h    : outparam;

    __shared__ float sa[TN][IN];
    __shared__ float sx[TN][IN];

    const int node0 = blockIdx.x * TN;   // N_NODES divisible by TN (8, 16)

    // cooperative stage: agg/deg and raw input features
    for (int i = threadIdx.x; i < TN * IN; i += OUT) {
        int n = i / IN;
        int f = i - n * IN;
        int node = node0 + n;
        float dg = fmaxf(__ldg(&g_deg[node]), 1.0f);
        sa[n][f] = __ldg(&agg[(size_t)node * IN + f]) / dg;
        sx[n][f] = __ldg(&xin[(size_t)node * IN + f]);
    }
    __syncthreads();

    const int o = threadIdx.x;           // blockDim.x == OUT
    float bv = __ldg(&bias[o]);
    float acc[TN];
    #pragma unroll
    for (int n = 0; n < TN; n++) acc[n] = bv;

    const float* wlrow = wl + o * IN;
    const float* wrrow = wr + o * IN;

    #pragma unroll 4
    for (int f = 0; f < IN; f++) {
        float wlv = __ldg(&wlrow[f]);
        float wrv = __ldg(&wrrow[f]);
        #pragma unroll
        for (int n = 0; n < TN; n++)
            acc[n] += wlv * sa[n][f] + wrv * sx[n][f];
    }

    #pragma unroll
    for (int n = 0; n < TN; n++) {
        float v = acc[n];
        if (RELU) v = fmaxf(v, 0.0f);
        out[(size_t)(node0 + n) * OUT + o] = v;
    }
}

// ---------------------------------------------------------------------------
// Launch sequence (graph-capturable: kernel launches only).
// ---------------------------------------------------------------------------
extern "C" void kernel_launch(void* const* d_in, const int* in_sizes, int n_in,
                              void* d_out, int out_size) {
    const float* x   = (const float*)d_in[0];
    const void*  ei  = d_in[1];
    const float* w1l = (const float*)d_in[2];
    const float* b1  = (const float*)d_in[3];
    const float* w1r = (const float*)d_in[4];
    const float* w2l = (const float*)d_in[5];
    const float* b2  = (const float*)d_in[6];
    const float* w2r = (const float*)d_in[7];
    float* out = (float*)d_out;

    const int E = in_sizes[1] / 2;       // 800000 (count identical for i32/i64)

    detect_kernel<<<1, 32>>>(ei);
    zero_kernel<<<2048, 256>>>();
    prep_w<<<64, 256>>>(w1l, w1r, w2l, w2r);

    // Layer 1: scatter mean-agg of x, then fused linear + relu -> g_h
    scatter_kernel<F0, true><<<(E + 7) / 8, 256>>>(x, ei, E);
    linear_kernel<true, F0, F1, 8, true><<<N_NODES / 8, F1>>>(x, b1, nullptr);

    // Layer 2: scatter mean-agg of h, then fused linear -> d_out
    scatter_kernel<F1, false><<<(E + 7) / 8, 256>>>(nullptr, ei, E);
    linear_kernel<false, F1, F2, 16, false><<<N_NODES / 16, F2>>>(nullptr, b2, out);
}

// round 5
// speedup vs baseline: 4.3639x; 4.3639x over previous
#include <cuda_runtime.h>

#define N_NODES 50000
#define F0 96
#define F1 128
#define F2 64

// ---- persistent scratch (alloc-free per harness rules) ----
__device__ float g_agg1[N_NODES * F0];   // mean-agg input features, layer 1
__device__ float g_h   [N_NODES * F1];   // hidden activations
__device__ float g_agg2[N_NODES * F1];   // mean-agg hidden, layer 2
__device__ float g_deg [N_NODES];        // in-degree (shared across layers)
// Presigned weights stored TRANSPOSED: [IN][OUT] so lane o reads coalesced.
__device__ float g_w1l[F0 * F1];
__device__ float g_w1r[F0 * F1];
__device__ float g_w2l[F1 * F2];
__device__ float g_w2r[F1 * F2];
__device__ int   g_is64;                 // edge_index dtype flag

// ---------------------------------------------------------------------------
// Vectorized global reduction (sm_90+): 16B atomic add, 4x fewer L2 atomic ops.
// ---------------------------------------------------------------------------
__device__ __forceinline__ void red_add_v4(float* addr, float4 v) {
    asm volatile("red.global.add.v4.f32 [%0], {%1, %2, %3, %4};"
                 :: "l"(addr), "f"(v.x), "f"(v.y), "f"(v.z), "f"(v.w)
                 : "memory");
}

// ---------------------------------------------------------------------------
// Detect whether edge_index is int64 or int32 (JAX canonicalizes int64->int32
// unless x64 is enabled). If data is int32, interpreting as int64 yields
// values outside [0, N_NODES) with overwhelming probability.
// ---------------------------------------------------------------------------
__global__ void detect_kernel(const void* __restrict__ ei) {
    if (threadIdx.x == 0 && blockIdx.x == 0) {
        const long long* p = (const long long*)ei;
        int ok = 1;
        #pragma unroll
        for (int i = 0; i < 8; i++) {
            long long v = p[i];
            if (v < 0 || v >= N_NODES) ok = 0;
        }
        g_is64 = ok;
    }
}

// ---------------------------------------------------------------------------
// Zero the accumulation buffers (scratch persists across graph replays).
// float4 stores; all three regions are 16B-aligned and size%4==0.
// ---------------------------------------------------------------------------
__global__ void zero_kernel() {
    const int q1 = N_NODES * F0 / 4;     // agg1 float4 count
    const int q2 = N_NODES * F1 / 4;     // agg2 float4 count
    const int q3 = N_NODES / 4;          // deg  float4 count (50000%4==0)
    const int total = q1 + q2 + q3;
    const float4 z = make_float4(0.f, 0.f, 0.f, 0.f);
    for (int i = blockIdx.x * blockDim.x + threadIdx.x; i < total;
         i += gridDim.x * blockDim.x) {
        if (i < q1)            ((float4*)g_agg1)[i] = z;
        else if (i < q1 + q2)  ((float4*)g_agg2)[i - q1] = z;
        else                   ((float4*)g_deg)[i - q1 - q2] = z;
    }
}

// ---------------------------------------------------------------------------
// Presign + transpose weights: g_wT[f*OUT + o] = sign(w[o*IN + f]).
// ---------------------------------------------------------------------------
__global__ void prep_w(const float* __restrict__ w1l, const float* __restrict__ w1r,
                       const float* __restrict__ w2l, const float* __restrict__ w2r) {
    const int s12 = F1 * F0;          // 12288
    const int s34 = F2 * F1;          // 8192
    const int total = 2 * s12 + 2 * s34;
    for (int i = blockIdx.x * blockDim.x + threadIdx.x; i < total;
         i += gridDim.x * blockDim.x) {
        const float* srcw; float* dstw; int IN, OUT, j;
        if (i < s12)                { srcw = w1l; dstw = g_w1l; IN = F0; OUT = F1; j = i; }
        else if (i < 2 * s12)       { srcw = w1r; dstw = g_w1r; IN = F0; OUT = F1; j = i - s12; }
        else if (i < 2 * s12 + s34) { srcw = w2l; dstw = g_w2l; IN = F1; OUT = F2; j = i - 2 * s12; }
        else                        { srcw = w2r; dstw = g_w2r; IN = F1; OUT = F2; j = i - 2 * s12 - s34; }
        int o = j / IN;
        int f = j - o * IN;
        float w = srcw[j];
        dstw[f * OUT + o] = (w > 0.0f) ? 1.0f : ((w < 0.0f) ? -1.0f : 0.0f);
    }
}

// ---------------------------------------------------------------------------
// Edge scatter: one warp per edge, one float4 per lane.
// F=96 -> lanes 0..23 active; F=128 -> all 32 lanes.
// Layer 1 also accumulates the in-degree (reused by layer 2).
// ---------------------------------------------------------------------------
template <int F, bool L1>
__global__ void scatter_kernel(const float* __restrict__ xin,
                               const void* __restrict__ ei, int E) {
    int e = blockIdx.x * (blockDim.x >> 5) + (threadIdx.x >> 5);
    if (e >= E) return;
    int lane = threadIdx.x & 31;

    int s, d;
    if (g_is64) {
        const long long* p = (const long long*)ei;
        s = (int)__ldg(&p[e]);
        d = (int)__ldg(&p[E + e]);
    } else {
        const int* p = (const int*)ei;
        s = __ldg(&p[e]);
        d = __ldg(&p[E + e]);
    }

    const float* src_row = (L1 ? xin : (const float*)g_h) + (size_t)s * F;
    float*       dst_row = (L1 ? g_agg1 : g_agg2)          + (size_t)d * F;

    if (lane * 4 < F) {
        float4 v = __ldg((const float4*)src_row + lane);
        red_add_v4((float*)((float4*)dst_row + lane), v);
    }

    if (L1 && lane == 0)
        atomicAdd(&g_deg[d], 1.0f);
}

// ---------------------------------------------------------------------------
// Fused SAGE linear:
//   out[i] = (agg[i]/max(deg,1)) @ sgn(Wl)^T + b + xin[i] @ sgn(Wr)^T
// Block = OUT threads (one output column each), TN nodes staged in shared.
// Weight loads are coalesced ([IN][OUT] layout, L1-resident);
// shared reads are warp-broadcast (all lanes same address), conflict-free.
// ---------------------------------------------------------------------------
template <bool L1Flag, int IN, int OUT, int TN, bool RELU>
__global__ void linear_kernel(const float* __restrict__ xparam,
                              const float* __restrict__ bias,
                              float* __restrict__ outparam) {
    const float* agg = L1Flag ? g_agg1 : g_agg2;
    const float* xin = L1Flag ? xparam : (const float*)g_h;
    const float* wlT = L1Flag ? g_w1l  : g_w2l;    // [IN][OUT]
    const float* wrT = L1Flag ? g_w1r  : g_w2r;    // [IN][OUT]
    float*       out = L1Flag ? g_h    : outparam;

    __shared__ float sa[TN][IN];
    __shared__ float sx[TN][IN];

    const int node0 = blockIdx.x * TN;   // N_NODES divisible by TN

    // cooperative stage (float4): mean-normalized agg and raw input features
    const int Q = IN / 4;
    for (int i = threadIdx.x; i < TN * Q; i += OUT) {
        int n = i / Q;
        int q = i - n * Q;
        int node = node0 + n;
        float inv = 1.0f / fmaxf(__ldg(&g_deg[node]), 1.0f);
        float4 a = __ldg((const float4*)(agg + (size_t)node * IN) + q);
        float4 xv = __ldg((const float4*)(xin + (size_t)node * IN) + q);
        a.x *= inv; a.y *= inv; a.z *= inv; a.w *= inv;
        *(float4*)&sa[n][q * 4] = a;
        *(float4*)&sx[n][q * 4] = xv;
    }
    __syncthreads();

    const int o = threadIdx.x;           // blockDim.x == OUT
    float bv = __ldg(&bias[o]);
    float acc[TN];
    #pragma unroll
    for (int n = 0; n < TN; n++) acc[n] = bv;

    #pragma unroll 8
    for (int f = 0; f < IN; f++) {
        float wlv = __ldg(&wlT[f * OUT + o]);   // coalesced, L1-hit
        float wrv = __ldg(&wrT[f * OUT + o]);
        #pragma unroll
        for (int n = 0; n < TN; n++)
            acc[n] += wlv * sa[n][f] + wrv * sx[n][f];
    }

    #pragma unroll
    for (int n = 0; n < TN; n++) {
        float v = acc[n];
        if (RELU) v = fmaxf(v, 0.0f);
        out[(size_t)(node0 + n) * OUT + o] = v;
    }
}

// ---------------------------------------------------------------------------
// Launch sequence (graph-capturable: kernel launches only).
// ---------------------------------------------------------------------------
extern "C" void kernel_launch(void* const* d_in, const int* in_sizes, int n_in,
                              void* d_out, int out_size) {
    const float* x   = (const float*)d_in[0];
    const void*  ei  = d_in[1];
    const float* w1l = (const float*)d_in[2];
    const float* b1  = (const float*)d_in[3];
    const float* w1r = (const float*)d_in[4];
    const float* w2l = (const float*)d_in[5];
    const float* b2  = (const float*)d_in[6];
    const float* w2r = (const float*)d_in[7];
    float* out = (float*)d_out;

    const int E = in_sizes[1] / 2;       // 800000 (count identical for i32/i64)

    detect_kernel<<<1, 32>>>(ei);
    zero_kernel<<<2048, 256>>>();
    prep_w<<<64, 256>>>(w1l, w1r, w2l, w2r);

    // Layer 1: scatter mean-agg of x, then fused linear + relu -> g_h
    scatter_kernel<F0, true><<<(E + 7) / 8, 256>>>(x, ei, E);
    linear_kernel<true, F0, F1, 16, true><<<N_NODES / 16, F1>>>(x, b1, nullptr);

    // Layer 2: scatter mean-agg of h, then fused linear -> d_out
    scatter_kernel<F1, false><<<(E + 7) / 8, 256>>>(nullptr, ei, E);
    linear_kernel<false, F1, F2, 16, false><<<N_NODES / 16, F2>>>(nullptr, b2, out);
}

// round 8
// speedup vs baseline: 4.9805x; 1.1413x over previous
#include <cuda_runtime.h>

#define N_NODES 50000
#define F0 96
#define F1 128
#define F2 64
#define E_CAP 1000000

// ---- persistent scratch (alloc-free per harness rules) ----
__device__ float g_agg1[N_NODES * F0];    // mean-agg input features, layer 1 (pre-normalized)
__device__ float g_h   [N_NODES * F1];    // hidden activations
__device__ float g_agg2[N_NODES * F1];    // mean-agg hidden, layer 2 (pre-normalized)
__device__ int   g_rowptr[N_NODES + 1];   // CSR row pointers (by dst)
__device__ int   g_cnt[N_NODES];          // histogram / fill cursor
__device__ int   g_esrc[E_CAP];           // edge sources bucketed by dst
// Presigned weights stored TRANSPOSED: [IN][OUT] so lane o reads coalesced.
__device__ float g_w1l[F0 * F1];
__device__ float g_w1r[F0 * F1];
__device__ float g_w2l[F1 * F2];
__device__ float g_w2r[F1 * F2];
__device__ int   g_is64;                  // edge_index dtype flag

// ---------------------------------------------------------------------------
// f32x2 packed-FMA helpers (sm_103a: 2x fp32 FMA throughput, full precision)
// ---------------------------------------------------------------------------
__device__ __forceinline__ unsigned long long pack2dup(float v) {
    unsigned long long r;
    asm("mov.b64 %0, {%1, %1};" : "=l"(r) : "f"(v));
    return r;
}
__device__ __forceinline__ void fma2(unsigned long long& d,
                                     unsigned long long a,
                                     unsigned long long b) {
    asm("fma.rn.f32x2 %0, %1, %2, %0;" : "+l"(d) : "l"(a), "l"(b));
}
__device__ __forceinline__ float2 unpack2(unsigned long long v) {
    float2 f;
    asm("mov.b64 {%0, %1}, %2;" : "=f"(f.x), "=f"(f.y) : "l"(v));
    return f;
}

// ---------------------------------------------------------------------------
// Zero the histogram + detect edge-index dtype (JAX canonicalizes int64->int32
// unless x64 is enabled; int32 data read as int64 lands outside [0,N) w.h.p.)
// ---------------------------------------------------------------------------
__global__ void zero_detect_kernel(const void* __restrict__ ei) {
    if (blockIdx.x == 0 && threadIdx.x == 0) {
        const long long* p = (const long long*)ei;
        int ok = 1;
        #pragma unroll
        for (int i = 0; i < 8; i++) {
            long long v = p[i];
            if (v < 0 || v >= N_NODES) ok = 0;
        }
        g_is64 = ok;
    }
    for (int i = blockIdx.x * blockDim.x + threadIdx.x; i < N_NODES;
         i += gridDim.x * blockDim.x)
        g_cnt[i] = 0;
}

// ---------------------------------------------------------------------------
// CSR build step 1: per-dst histogram.
// ---------------------------------------------------------------------------
__global__ void count_kernel(const void* __restrict__ ei, int E) {
    const int is64 = g_is64;
    for (int e = blockIdx.x * blockDim.x + threadIdx.x; e < E;
         e += gridDim.x * blockDim.x) {
        int d = is64 ? (int)__ldg((const long long*)ei + E + e)
                     : __ldg((const int*)ei + E + e);
        atomicAdd(&g_cnt[d], 1);
    }
}

// ---------------------------------------------------------------------------
// CSR build step 2: single-block exclusive scan of g_cnt -> g_rowptr,
// and reset g_cnt to 0 (reused as fill cursor).
// ---------------------------------------------------------------------------
__global__ void scan_kernel() {
    __shared__ int ssum[1024];
    const int C = (N_NODES + 1023) / 1024;   // 49
    const int t = threadIdx.x;
    const int base = t * C;

    int local = 0;
    for (int i = 0; i < C; i++) {
        int idx = base + i;
        if (idx < N_NODES) local += g_cnt[idx];
    }
    ssum[t] = local;
    __syncthreads();

    // Hillis-Steele inclusive scan (uniform control flow)
    #pragma unroll
    for (int off = 1; off < 1024; off <<= 1) {
        int v = (t >= off) ? ssum[t - off] : 0;
        __syncthreads();
        ssum[t] += v;
        __syncthreads();
    }

    int run = ssum[t] - local;   // exclusive prefix
    for (int i = 0; i < C; i++) {
        int idx = base + i;
        if (idx < N_NODES) {
            int c = g_cnt[idx];
            g_rowptr[idx] = run;
            run += c;
            g_cnt[idx] = 0;
        }
    }
    if (t == 1023) g_rowptr[N_NODES] = run;
}

// ---------------------------------------------------------------------------
// CSR build step 3: bucket edge sources by dst.
// ---------------------------------------------------------------------------
__global__ void fill_kernel(const void* __restrict__ ei, int E) {
    const int is64 = g_is64;
    for (int e = blockIdx.x * blockDim.x + threadIdx.x; e < E;
         e += gridDim.x * blockDim.x) {
        int s, d;
        if (is64) {
            s = (int)__ldg((const long long*)ei + e);
            d = (int)__ldg((const long long*)ei + E + e);
        } else {
            s = __ldg((const int*)ei + e);
            d = __ldg((const int*)ei + E + e);
        }
        int pos = g_rowptr[d] + atomicAdd(&g_cnt[d], 1);
        g_esrc[pos] = s;
    }
}

// ---------------------------------------------------------------------------
// Mean aggregation via CSR gather: one warp per node, no atomics.
// Lane l accumulates feature chunk [4l, 4l+4). Writes pre-normalized mean.
// ---------------------------------------------------------------------------
template <int F, bool L1>
__global__ void gather_kernel(const float* __restrict__ xin) {
    const float* src = L1 ? xin : (const float*)g_h;
    float*       agg = L1 ? g_agg1 : g_agg2;

    const int warps = blockDim.x >> 5;
    const int node = blockIdx.x * warps + (threadIdx.x >> 5);
    if (node >= N_NODES) return;
    const int lane = threadIdx.x & 31;
    const bool active = (lane * 4) < F;

    const int beg = __ldg(&g_rowptr[node]);
    const int end = __ldg(&g_rowptr[node + 1]);

    float4 acc = make_float4(0.f, 0.f, 0.f, 0.f);
    for (int j0 = beg; j0 < end; j0 += 32) {
        const int kmax = min(32, end - j0);
        int idx = (lane < kmax) ? __ldg(&g_esrc[j0 + lane]) : 0;
        #pragma unroll 4
        for (int k = 0; k < kmax; k++) {
            int s = __shfl_sync(0xffffffffu, idx, k);
            if (active) {
                float4 v = __ldg((const float4*)(src + (size_t)s * F) + lane);
                acc.x += v.x; acc.y += v.y; acc.z += v.z; acc.w += v.w;
            }
        }
    }
    if (active) {
        float inv = 1.0f / fmaxf((float)(end - beg), 1.0f);
        acc.x *= inv; acc.y *= inv; acc.z *= inv; acc.w *= inv;
        *((float4*)(agg + (size_t)node * F) + lane) = acc;
    }
}

// ---------------------------------------------------------------------------
// Presign + transpose weights: g_wT[f*OUT + o] = sign(w[o*IN + f]).
// ---------------------------------------------------------------------------
__global__ void prep_w(const float* __restrict__ w1l, const float* __restrict__ w1r,
                       const float* __restrict__ w2l, const float* __restrict__ w2r) {
    const int s12 = F1 * F0;
    const int s34 = F2 * F1;
    const int total = 2 * s12 + 2 * s34;
    for (int i = blockIdx.x * blockDim.x + threadIdx.x; i < total;
         i += gridDim.x * blockDim.x) {
        const float* srcw; float* dstw; int IN, OUT, j;
        if (i < s12)                { srcw = w1l; dstw = g_w1l; IN = F0; OUT = F1; j = i; }
        else if (i < 2 * s12)       { srcw = w1r; dstw = g_w1r; IN = F0; OUT = F1; j = i - s12; }
        else if (i < 2 * s12 + s34) { srcw = w2l; dstw = g_w2l; IN = F1; OUT = F2; j = i - 2 * s12; }
        else                        { srcw = w2r; dstw = g_w2r; IN = F1; OUT = F2; j = i - 2 * s12 - s34; }
        int o = j / IN;
        int f = j - o * IN;
        float w = srcw[j];
        dstw[f * OUT + o] = (w > 0.0f) ? 1.0f : ((w < 0.0f) ? -1.0f : 0.0f);
    }
}

// ---------------------------------------------------------------------------
// Fused SAGE linear with packed f32x2 FMA:
//   out[i] = mean_agg[i] @ sgn(Wl)^T + b + xin[i] @ sgn(Wr)^T
// Smem staged TRANSPOSED [IN][TN]: one LDS.128 feeds 4 nodes (broadcast,
// conflict-free). Accumulators are f32x2 pairs; smem read as ulonglong2 so
// packed operands need no movs. Weight loads coalesced ([IN][OUT]).
// ---------------------------------------------------------------------------
template <bool L1Flag, int IN, int OUT, int TN, bool RELU>
__global__ void linear_kernel(const float* __restrict__ xparam,
                              const float* __restrict__ bias,
                              float* __restrict__ outparam) {
    const float* agg = L1Flag ? g_agg1 : g_agg2;          // pre-normalized
    const float* xin = L1Flag ? xparam : (const float*)g_h;
    const float* wlT = L1Flag ? g_w1l  : g_w2l;           // [IN][OUT]
    const float* wrT = L1Flag ? g_w1r  : g_w2r;           // [IN][OUT]
    float*       out = L1Flag ? g_h    : outparam;

    __shared__ __align__(16) float sa[IN][TN];
    __shared__ __align__(16) float sx[IN][TN];

    const int node0 = blockIdx.x * TN;    // N_NODES divisible by TN=16
    const int Q = IN / 4;

    // stage transposed: thread i handles (n = i % TN, q = i / TN)
    for (int i = threadIdx.x; i < TN * Q; i += OUT) {
        int n = i & (TN - 1);
        int q = i / TN;
        int node = node0 + n;
        float4 a  = __ldg((const float4*)(agg + (size_t)node * IN) + q);
        float4 xv = __ldg((const float4*)(xin + (size_t)node * IN) + q);
        sa[4 * q + 0][n] = a.x;  sa[4 * q + 1][n] = a.y;
        sa[4 * q + 2][n] = a.z;  sa[4 * q + 3][n] = a.w;
        sx[4 * q + 0][n] = xv.x; sx[4 * q + 1][n] = xv.y;
        sx[4 * q + 2][n] = xv.z; sx[4 * q + 3][n] = xv.w;
    }
    __syncthreads();

    const int o = threadIdx.x;            // blockDim.x == OUT
    const float bv = __ldg(&bias[o]);
    unsigned long long acc[TN / 2];
    const unsigned long long b2 = pack2dup(bv);
    #pragma unroll
    for (int p = 0; p < TN / 2; p++) acc[p] = b2;

    #pragma unroll 4
    for (int f = 0; f < IN; f++) {
        unsigned long long wl2 = pack2dup(__ldg(&wlT[f * OUT + o]));
        unsigned long long wr2 = pack2dup(__ldg(&wrT[f * OUT + o]));
        #pragma unroll
        for (int p = 0; p < TN / 4; p++) {
            ulonglong2 va = *(const ulonglong2*)&sa[f][4 * p];
            ulonglong2 vx = *(const ulonglong2*)&sx[f][4 * p];
            fma2(acc[2 * p + 0], va.x, wl2);
            fma2(acc[2 * p + 1], va.y, wl2);
            fma2(acc[2 * p + 0], vx.x, wr2);
            fma2(acc[2 * p + 1], vx.y, wr2);
        }
    }

    #pragma unroll
    for (int p = 0; p < TN / 2; p++) {
        float2 r = unpack2(acc[p]);
        if (RELU) { r.x = fmaxf(r.x, 0.f); r.y = fmaxf(r.y, 0.f); }
        out[(size_t)(node0 + 2 * p + 0) * OUT + o] = r.x;
        out[(size_t)(node0 + 2 * p + 1) * OUT + o] = r.y;
    }
}

// ---------------------------------------------------------------------------
// Launch sequence (graph-capturable: kernel launches only).
// ---------------------------------------------------------------------------
extern "C" void kernel_launch(void* const* d_in, const int* in_sizes, int n_in,
                              void* d_out, int out_size) {
    const float* x   = (const float*)d_in[0];
    const void*  ei  = d_in[1];
    const float* w1l = (const float*)d_in[2];
    const float* b1  = (const float*)d_in[3];
    const float* w1r = (const float*)d_in[4];
    const float* w2l = (const float*)d_in[5];
    const float* b2  = (const float*)d_in[6];
    const float* w2r = (const float*)d_in[7];
    float* out = (float*)d_out;

    const int E = in_sizes[1] / 2;        // 800000

    // CSR build (per launch; scratch is not assumed clean across replays)
    zero_detect_kernel<<<128, 256>>>(ei);
    count_kernel<<<1024, 256>>>(ei, E);
    scan_kernel<<<1, 1024>>>();
    fill_kernel<<<1024, 256>>>(ei, E);
    prep_w<<<64, 256>>>(w1l, w1r, w2l, w2r);

    // Layer 1: mean-gather of x, then fused linear + relu -> g_h
    gather_kernel<F0, true><<<(N_NODES + 7) / 8, 256>>>(x);
    linear_kernel<true, F0, F1, 16, true><<<N_NODES / 16, F1>>>(x, b1, nullptr);

    // Layer 2: mean-gather of h, then fused linear -> d_out
    gather_kernel<F1, false><<<(N_NODES + 7) / 8, 256>>>(nullptr);
    linear_kernel<false, F1, F2, 16, false><<<N_NODES / 16, F2>>>(nullptr, b2, out);
}

// round 9
// speedup vs baseline: 5.4194x; 1.0881x over previous
#include <cuda_runtime.h>

#define N_NODES 50000
#define F0 96
#define F1 128
#define F2 64
#define E_CAP 1000000

typedef unsigned long long ull;

// ---- persistent scratch (alloc-free per harness rules) ----
__device__ float g_agg1[N_NODES * F0];    // mean-agg of x (pre-normalized)
__device__ float g_h   [N_NODES * F1];    // hidden activations
__device__ float g_z   [N_NODES * F2];    // h @ sgn(W2l)^T  (pre-aggregation)
__device__ float g_r   [N_NODES * F2];    // h @ sgn(W2r)^T  (self term)
__device__ int   g_rowptr[N_NODES + 1];   // CSR row pointers (by dst)
__device__ int   g_cnt[N_NODES];          // histogram / fill cursor
__device__ int   g_esrc[E_CAP];           // edge sources bucketed by dst
// Presigned weights stored TRANSPOSED: [IN][OUT] so lane o reads coalesced.
__device__ float g_w1l[F0 * F1];
__device__ float g_w1r[F0 * F1];
__device__ float g_w2l[F1 * F2];
__device__ float g_w2r[F1 * F2];
__device__ int   g_is64;                  // edge_index dtype flag

// ---------------------------------------------------------------------------
// Packed f32x2 helpers (sm_103a: 2x fp32 pipe throughput, full fp32 precision)
// ---------------------------------------------------------------------------
__device__ __forceinline__ ull pack2dup(float v) {
    ull r; asm("mov.b64 %0, {%1, %1};" : "=l"(r) : "f"(v)); return r;
}
__device__ __forceinline__ void fma2(ull& d, ull a, ull b) {
    asm("fma.rn.f32x2 %0, %1, %2, %0;" : "+l"(d) : "l"(a), "l"(b));
}
__device__ __forceinline__ void add2(ull& d, ull a) {
    asm("add.rn.f32x2 %0, %0, %1;" : "+l"(d) : "l"(a));
}
__device__ __forceinline__ float2 unpack2(ull v) {
    float2 f; asm("mov.b64 {%0, %1}, %2;" : "=f"(f.x), "=f"(f.y) : "l"(v)); return f;
}

// ---------------------------------------------------------------------------
// Merged prep: zero histogram, detect edge dtype, presign+transpose weights.
// (JAX canonicalizes int64->int32 unless x64 enabled; int32 data read as
//  int64 lands outside [0,N) with overwhelming probability.)
// ---------------------------------------------------------------------------
__global__ void prep_kernel(const void* __restrict__ ei,
                            const float* __restrict__ w1l, const float* __restrict__ w1r,
                            const float* __restrict__ w2l, const float* __restrict__ w2r) {
    if (blockIdx.x == 0 && threadIdx.x == 0) {
        const long long* p = (const long long*)ei;
        int ok = 1;
        #pragma unroll
        for (int i = 0; i < 8; i++) {
            long long v = p[i];
            if (v < 0 || v >= N_NODES) ok = 0;
        }
        g_is64 = ok;
    }
    const int s12 = F1 * F0;              // 12288
    const int s34 = F2 * F1;              // 8192
    const int wtot = 2 * s12 + 2 * s34;   // 40960
    const int total = wtot + N_NODES;
    for (int i = blockIdx.x * blockDim.x + threadIdx.x; i < total;
         i += gridDim.x * blockDim.x) {
        if (i >= wtot) { g_cnt[i - wtot] = 0; continue; }
        const float* srcw; float* dstw; int IN, OUT, j;
        if (i < s12)                { srcw = w1l; dstw = g_w1l; IN = F0; OUT = F1; j = i; }
        else if (i < 2 * s12)       { srcw = w1r; dstw = g_w1r; IN = F0; OUT = F1; j = i - s12; }
        else if (i < 2 * s12 + s34) { srcw = w2l; dstw = g_w2l; IN = F1; OUT = F2; j = i - 2 * s12; }
        else                        { srcw = w2r; dstw = g_w2r; IN = F1; OUT = F2; j = i - 2 * s12 - s34; }
        int o = j / IN;
        int f = j - o * IN;
        float w = srcw[j];
        dstw[f * OUT + o] = (w > 0.0f) ? 1.0f : ((w < 0.0f) ? -1.0f : 0.0f);
    }
}

// ---------------------------------------------------------------------------
// CSR build step 1: per-dst histogram (REDG, no return).
// ---------------------------------------------------------------------------
__global__ void count_kernel(const void* __restrict__ ei, int E) {
    const int is64 = g_is64;
    for (int e = blockIdx.x * blockDim.x + threadIdx.x; e < E;
         e += gridDim.x * blockDim.x) {
        int d = is64 ? (int)__ldg((const long long*)ei + E + e)
                     : __ldg((const int*)ei + E + e);
        atomicAdd(&g_cnt[d], 1);
    }
}

// ---------------------------------------------------------------------------
// CSR build step 2: single-block exclusive scan -> rowptr; reset cnt.
// ---------------------------------------------------------------------------
__global__ void scan_kernel() {
    __shared__ int ssum[1024];
    const int C = (N_NODES + 1023) / 1024;   // 49
    const int t = threadIdx.x;
    const int base = t * C;

    int local = 0;
    for (int i = 0; i < C; i++) {
        int idx = base + i;
        if (idx < N_NODES) local += g_cnt[idx];
    }
    ssum[t] = local;
    __syncthreads();

    #pragma unroll
    for (int off = 1; off < 1024; off <<= 1) {
        int v = (t >= off) ? ssum[t - off] : 0;
        __syncthreads();
        ssum[t] += v;
        __syncthreads();
    }

    int run = ssum[t] - local;
    for (int i = 0; i < C; i++) {
        int idx = base + i;
        if (idx < N_NODES) {
            int c = g_cnt[idx];
            g_rowptr[idx] = run;
            run += c;
            g_cnt[idx] = 0;
        }
    }
    if (t == 1023) g_rowptr[N_NODES] = run;
}

// ---------------------------------------------------------------------------
// CSR build step 3: bucket edge sources by dst.
// ---------------------------------------------------------------------------
__global__ void fill_kernel(const void* __restrict__ ei, int E) {
    const int is64 = g_is64;
    for (int e = blockIdx.x * blockDim.x + threadIdx.x; e < E;
         e += gridDim.x * blockDim.x) {
        int s, d;
        if (is64) {
            s = (int)__ldg((const long long*)ei + e);
            d = (int)__ldg((const long long*)ei + E + e);
        } else {
            s = __ldg((const int*)ei + e);
            d = __ldg((const int*)ei + E + e);
        }
        int pos = g_rowptr[d] + atomicAdd(&g_cnt[d], 1);
        g_esrc[pos] = s;
    }
}

// ---------------------------------------------------------------------------
// Layer-1 mean gather: warp per node, lane = float4 chunk (24 active lanes).
// Shuffle-free: 4 neighbor indices loaded directly (L1 broadcast), 4
// independent row loads into 4 accumulators -> explicit MLP>=4.
// ---------------------------------------------------------------------------
__global__ void gather1_kernel(const float* __restrict__ x) {
    const int node = blockIdx.x * (blockDim.x >> 5) + (threadIdx.x >> 5);
    if (node >= N_NODES) return;
    const int lane = threadIdx.x & 31;
    const bool act = lane < (F0 / 4);

    const int beg = __ldg(&g_rowptr[node]);
    const int end = __ldg(&g_rowptr[node + 1]);

    float4 a0 = {0,0,0,0}, a1 = {0,0,0,0}, a2 = {0,0,0,0}, a3 = {0,0,0,0};
    int j = beg;
    for (; j + 4 <= end; j += 4) {
        int s0 = __ldg(&g_esrc[j + 0]);
        int s1 = __ldg(&g_esrc[j + 1]);
        int s2 = __ldg(&g_esrc[j + 2]);
        int s3 = __ldg(&g_esrc[j + 3]);
        if (act) {
            float4 v0 = __ldg((const float4*)(x + (size_t)s0 * F0) + lane);
            float4 v1 = __ldg((const float4*)(x + (size_t)s1 * F0) + lane);
            float4 v2 = __ldg((const float4*)(x + (size_t)s2 * F0) + lane);
            float4 v3 = __ldg((const float4*)(x + (size_t)s3 * F0) + lane);
            a0.x += v0.x; a0.y += v0.y; a0.z += v0.z; a0.w += v0.w;
            a1.x += v1.x; a1.y += v1.y; a1.z += v1.z; a1.w += v1.w;
            a2.x += v2.x; a2.y += v2.y; a2.z += v2.z; a2.w += v2.w;
            a3.x += v3.x; a3.y += v3.y; a3.z += v3.z; a3.w += v3.w;
        }
    }
    for (; j < end; j++) {
        int s = __ldg(&g_esrc[j]);
        if (act) {
            float4 v = __ldg((const float4*)(x + (size_t)s * F0) + lane);
            a0.x += v.x; a0.y += v.y; a0.z += v.z; a0.w += v.w;
        }
    }
    if (act) {
        float inv = 1.0f / fmaxf((float)(end - beg), 1.0f);
        float4 r;
        r.x = (a0.x + a1.x + a2.x + a3.x) * inv;
        r.y = (a0.y + a1.y + a2.y + a3.y) * inv;
        r.z = (a0.z + a1.z + a2.z + a3.z) * inv;
        r.w = (a0.w + a1.w + a2.w + a3.w) * inv;
        *((float4*)(g_agg1 + (size_t)node * F0) + lane) = r;
    }
}

// ---------------------------------------------------------------------------
// Layer-1 fused linear (f32x2 FMA):
//   h = relu(agg1 @ sgn(W1l)^T + b1 + x @ sgn(W1r)^T)
// Smem staged transposed [IN][TN]; LDS.128 broadcast; weights coalesced.
// ---------------------------------------------------------------------------
template <int IN, int OUT, int TN>
__global__ void linear1_kernel(const float* __restrict__ xin,
                               const float* __restrict__ bias) {
    __shared__ __align__(16) float sa[IN][TN];
    __shared__ __align__(16) float sx[IN][TN];

    const int node0 = blockIdx.x * TN;
    const int Q = IN / 4;

    for (int i = threadIdx.x; i < TN * Q; i += OUT) {
        int n = i & (TN - 1);
        int q = i / TN;
        int node = node0 + n;
        float4 a  = __ldg((const float4*)(g_agg1 + (size_t)node * IN) + q);
        float4 xv = __ldg((const float4*)(xin    + (size_t)node * IN) + q);
        sa[4 * q + 0][n] = a.x;  sa[4 * q + 1][n] = a.y;
        sa[4 * q + 2][n] = a.z;  sa[4 * q + 3][n] = a.w;
        sx[4 * q + 0][n] = xv.x; sx[4 * q + 1][n] = xv.y;
        sx[4 * q + 2][n] = xv.z; sx[4 * q + 3][n] = xv.w;
    }
    __syncthreads();

    const int o = threadIdx.x;            // blockDim.x == OUT == 128
    ull acc[TN / 2];
    const ull b2v = pack2dup(__ldg(&bias[o]));
    #pragma unroll
    for (int p = 0; p < TN / 2; p++) acc[p] = b2v;

    #pragma unroll 4
    for (int f = 0; f < IN; f++) {
        ull wl2 = pack2dup(__ldg(&g_w1l[f * OUT + o]));
        ull wr2 = pack2dup(__ldg(&g_w1r[f * OUT + o]));
        #pragma unroll
        for (int p = 0; p < TN / 4; p++) {
            ulonglong2 va = *(const ulonglong2*)&sa[f][4 * p];
            ulonglong2 vx = *(const ulonglong2*)&sx[f][4 * p];
            fma2(acc[2 * p + 0], va.x, wl2);
            fma2(acc[2 * p + 1], va.y, wl2);
            fma2(acc[2 * p + 0], vx.x, wr2);
            fma2(acc[2 * p + 1], vx.y, wr2);
        }
    }

    #pragma unroll
    for (int p = 0; p < TN / 2; p++) {
        float2 r = unpack2(acc[p]);
        r.x = fmaxf(r.x, 0.f); r.y = fmaxf(r.y, 0.f);
        g_h[(size_t)(node0 + 2 * p + 0) * OUT + o] = r.x;
        g_h[(size_t)(node0 + 2 * p + 1) * OUT + o] = r.y;
    }
}

// ---------------------------------------------------------------------------
// Layer-2 dual GEMM (transform BEFORE aggregation; mean-agg is linear):
//   z = h @ sgn(W2l)^T   (aggregated afterwards, 64-dim instead of 128-dim)
//   r = h @ sgn(W2r)^T   (self term, added in the final epilogue)
// Block 128 threads: group 0 -> z, group 1 -> r; both read one staged h tile.
// ---------------------------------------------------------------------------
__global__ void dual_gemm_kernel() {
    const int TN = 16;
    __shared__ __align__(16) float sh[F1][TN];

    const int node0 = blockIdx.x * TN;
    const int tid = threadIdx.x;          // 128
    const int Q = F1 / 4;                 // 32

    for (int i = tid; i < TN * Q; i += 128) {
        int n = i & (TN - 1);
        int q = i / TN;
        float4 v = __ldg((const float4*)(g_h + (size_t)(node0 + n) * F1) + q);
        sh[4 * q + 0][n] = v.x; sh[4 * q + 1][n] = v.y;
        sh[4 * q + 2][n] = v.z; sh[4 * q + 3][n] = v.w;
    }
    __syncthreads();

    const int grp = tid >> 6;             // 0: W2l->z, 1: W2r->r
    const int o = tid & 63;
    const float* wT = grp ? g_w2r : g_w2l;   // [F1][64]
    float* outp = grp ? g_r : g_z;

    ull acc[TN / 2];
    #pragma unroll
    for (int p = 0; p < TN / 2; p++) acc[p] = 0ull;

    #pragma unroll 4
    for (int f = 0; f < F1; f++) {
        ull w2 = pack2dup(__ldg(&wT[f * F2 + o]));
        #pragma unroll
        for (int p = 0; p < TN / 4; p++) {
            ulonglong2 v = *(const ulonglong2*)&sh[f][4 * p];
            fma2(acc[2 * p + 0], v.x, w2);
            fma2(acc[2 * p + 1], v.y, w2);
        }
    }

    #pragma unroll
    for (int p = 0; p < TN / 2; p++) {
        float2 r = unpack2(acc[p]);
        outp[(size_t)(node0 + 2 * p + 0) * F2 + o] = r.x;
        outp[(size_t)(node0 + 2 * p + 1) * F2 + o] = r.y;
    }
}

// ---------------------------------------------------------------------------
// Layer-2 gather + epilogue: out[i] = mean_{j in N(i)} z[j] + b2 + r[i].
// Warp per node, lane = f32x2 chunk (all 32 lanes active, 64 floats/row).
// Shuffle-free 4-way batched loads, packed adds.
// ---------------------------------------------------------------------------
__global__ void gather2_final_kernel(const float* __restrict__ b2,
                                     float* __restrict__ out) {
    const int node = blockIdx.x * (blockDim.x >> 5) + (threadIdx.x >> 5);
    if (node >= N_NODES) return;
    const int lane = threadIdx.x & 31;

    const int beg = __ldg(&g_rowptr[node]);
    const int end = __ldg(&g_rowptr[node + 1]);

    const ull* zb = (const ull*)g_z;      // row stride F2/2 = 32 ull
    ull a0 = 0, a1 = 0, a2 = 0, a3 = 0;
    int j = beg;
    for (; j + 4 <= end; j += 4) {
        int s0 = __ldg(&g_esrc[j + 0]);
        int s1 = __ldg(&g_esrc[j + 1]);
        int s2 = __ldg(&g_esrc[j + 2]);
        int s3 = __ldg(&g_esrc[j + 3]);
        ull v0 = __ldg(zb + (size_t)s0 * 32 + lane);
        ull v1 = __ldg(zb + (size_t)s1 * 32 + lane);
        ull v2 = __ldg(zb + (size_t)s2 * 32 + lane);
        ull v3 = __ldg(zb + (size_t)s3 * 32 + lane);
        add2(a0, v0); add2(a1, v1); add2(a2, v2); add2(a3, v3);
    }
    for (; j < end; j++) {
        int s = __ldg(&g_esrc[j]);
        add2(a0, __ldg(zb + (size_t)s * 32 + lane));
    }
    add2(a0, a1); add2(a2, a3); add2(a0, a2);

    float inv = 1.0f / fmaxf((float)(end - beg), 1.0f);
    float2 m = unpack2(a0);
    float2 bb = __ldg((const float2*)b2 + lane);
    float2 rr = __ldg((const float2*)g_r + (size_t)node * 32 + lane);
    float2 res;
    res.x = m.x * inv + bb.x + rr.x;
    res.y = m.y * inv + bb.y + rr.y;
    ((float2*)out)[(size_t)node * 32 + lane] = res;
}

// ---------------------------------------------------------------------------
// Launch sequence (graph-capturable: kernel launches only).
// ---------------------------------------------------------------------------
extern "C" void kernel_launch(void* const* d_in, const int* in_sizes, int n_in,
                              void* d_out, int out_size) {
    const float* x   = (const float*)d_in[0];
    const void*  ei  = d_in[1];
    const float* w1l = (const float*)d_in[2];
    const float* b1  = (const float*)d_in[3];
    const float* w1r = (const float*)d_in[4];
    const float* w2l = (const float*)d_in[5];
    const float* b2  = (const float*)d_in[6];
    const float* w2r = (const float*)d_in[7];
    float* out = (float*)d_out;

    const int E = in_sizes[1] / 2;        // 800000

    prep_kernel<<<128, 256>>>(ei, w1l, w1r, w2l, w2r);
    count_kernel<<<1024, 256>>>(ei, E);
    scan_kernel<<<1, 1024>>>();
    fill_kernel<<<1024, 256>>>(ei, E);

    gather1_kernel<<<(N_NODES + 7) / 8, 256>>>(x);
    linear1_kernel<F0, F1, 16><<<N_NODES / 16, F1>>>(x, b1);
    dual_gemm_kernel<<<N_NODES / 16, 128>>>();
    gather2_final_kernel<<<(N_NODES + 7) / 8, 256>>>(b2, out);
}

// round 10
// speedup vs baseline: 8.4306x; 1.5556x over previous
#include <cuda_runtime.h>

#define N_NODES 50000
#define F0 96
#define F1 128
#define F2 64
#define E_CAP 1000000
#define NB_SCAN 256
#define NPB 196              // nodes per scan block (256*196 >= 50000)

typedef unsigned long long ull;

// ---- persistent scratch (alloc-free per harness rules) ----
__device__ float g_agg1[N_NODES * F0];    // mean-agg of x (pre-normalized)
__device__ float g_z   [N_NODES * F2];    // h @ sgn(W2l)^T  (pre-aggregation)
__device__ float g_r   [N_NODES * F2];    // h @ sgn(W2r)^T  (self term)
__device__ int   g_rowptr[N_NODES + 1];   // CSR row pointers (by dst)
__device__ int   g_cnt[N_NODES];          // histogram / fill cursor
__device__ int   g_btot[NB_SCAN];         // scan block totals
__device__ int   g_boff[NB_SCAN];         // scan block offsets
__device__ int   g_esrc[E_CAP];           // edge sources bucketed by dst
// Presigned weights stored TRANSPOSED: [IN][OUT] so lane o reads coalesced.
__device__ float g_w1l[F0 * F1];
__device__ float g_w1r[F0 * F1];
__device__ float g_w2l[F1 * F2];
__device__ float g_w2r[F1 * F2];
__device__ int   g_is64;                  // edge_index dtype flag

// ---------------------------------------------------------------------------
// Packed f32x2 helpers (sm_103a: 2x fp32 pipe throughput, full fp32 precision)
// ---------------------------------------------------------------------------
__device__ __forceinline__ ull pack2dup(float v) {
    ull r; asm("mov.b64 %0, {%1, %1};" : "=l"(r) : "f"(v)); return r;
}
__device__ __forceinline__ void fma2(ull& d, ull a, ull b) {
    asm("fma.rn.f32x2 %0, %1, %2, %0;" : "+l"(d) : "l"(a), "l"(b));
}
__device__ __forceinline__ void add2(ull& d, ull a) {
    asm("add.rn.f32x2 %0, %0, %1;" : "+l"(d) : "l"(a));
}
__device__ __forceinline__ float2 unpack2(ull v) {
    float2 f; asm("mov.b64 {%0, %1}, %2;" : "=f"(f.x), "=f"(f.y) : "l"(v)); return f;
}
__device__ __forceinline__ ull pack2(float x, float y) {
    ull r; asm("mov.b64 %0, {%1, %2};" : "=l"(r) : "f"(x), "f"(y)); return r;
}

// ---------------------------------------------------------------------------
// Merged prep: zero histogram, detect edge dtype, presign+transpose weights.
// (JAX canonicalizes int64->int32 unless x64 enabled; int32 data read as
//  int64 lands outside [0,N) with overwhelming probability.)
// ---------------------------------------------------------------------------
__global__ void prep_kernel(const void* __restrict__ ei,
                            const float* __restrict__ w1l, const float* __restrict__ w1r,
                            const float* __restrict__ w2l, const float* __restrict__ w2r) {
    if (blockIdx.x == 0 && threadIdx.x == 0) {
        const long long* p = (const long long*)ei;
        int ok = 1;
        #pragma unroll
        for (int i = 0; i < 8; i++) {
            long long v = p[i];
            if (v < 0 || v >= N_NODES) ok = 0;
        }
        g_is64 = ok;
    }
    const int s12 = F1 * F0;              // 12288
    const int s34 = F2 * F1;              // 8192
    const int wtot = 2 * s12 + 2 * s34;   // 40960
    const int total = wtot + N_NODES;
    for (int i = blockIdx.x * blockDim.x + threadIdx.x; i < total;
         i += gridDim.x * blockDim.x) {
        if (i >= wtot) { g_cnt[i - wtot] = 0; continue; }
        const float* srcw; float* dstw; int IN, OUT, j;
        if (i < s12)                { srcw = w1l; dstw = g_w1l; IN = F0; OUT = F1; j = i; }
        else if (i < 2 * s12)       { srcw = w1r; dstw = g_w1r; IN = F0; OUT = F1; j = i - s12; }
        else if (i < 2 * s12 + s34) { srcw = w2l; dstw = g_w2l; IN = F1; OUT = F2; j = i - 2 * s12; }
        else                        { srcw = w2r; dstw = g_w2r; IN = F1; OUT = F2; j = i - 2 * s12 - s34; }
        int o = j / IN;
        int f = j - o * IN;
        float w = srcw[j];
        dstw[f * OUT + o] = (w > 0.0f) ? 1.0f : ((w < 0.0f) ? -1.0f : 0.0f);
    }
}

// ---------------------------------------------------------------------------
// CSR step 1: per-dst histogram.
// ---------------------------------------------------------------------------
__global__ void count_kernel(const void* __restrict__ ei, int E) {
    const int is64 = g_is64;
    for (int e = blockIdx.x * blockDim.x + threadIdx.x; e < E;
         e += gridDim.x * blockDim.x) {
        int d = is64 ? (int)__ldg((const long long*)ei + E + e)
                     : __ldg((const int*)ei + E + e);
        atomicAdd(&g_cnt[d], 1);
    }
}

// ---------------------------------------------------------------------------
// CSR step 2a: per-block local exclusive scan of cnt -> rowptr (local) + totals.
// ---------------------------------------------------------------------------
__global__ void scanA_kernel() {
    __shared__ int sv[256];
    const int b = blockIdx.x, t = threadIdx.x;
    const int node = b * NPB + t;
    int v = (t < NPB && node < N_NODES) ? g_cnt[node] : 0;
    sv[t] = v;
    __syncthreads();
    #pragma unroll
    for (int off = 1; off < 256; off <<= 1) {
        int u = (t >= off) ? sv[t - off] : 0;
        __syncthreads();
        sv[t] += u;
        __syncthreads();
    }
    if (t < NPB && node < N_NODES) g_rowptr[node] = sv[t] - v;   // local exclusive
    if (t == 255) g_btot[b] = sv[255];
}

// ---------------------------------------------------------------------------
// CSR step 2b: scan the 256 block totals.
// ---------------------------------------------------------------------------
__global__ void scanB_kernel() {
    __shared__ int sv[NB_SCAN];
    const int t = threadIdx.x;
    int v = g_btot[t];
    sv[t] = v;
    __syncthreads();
    #pragma unroll
    for (int off = 1; off < NB_SCAN; off <<= 1) {
        int u = (t >= off) ? sv[t - off] : 0;
        __syncthreads();
        sv[t] += u;
        __syncthreads();
    }
    g_boff[t] = sv[t] - v;
    if (t == NB_SCAN - 1) g_rowptr[N_NODES] = sv[t];
}

// ---------------------------------------------------------------------------
// CSR step 2c: globalize rowptr + reset cnt (fill cursor).
// ---------------------------------------------------------------------------
__global__ void scanC_kernel() {
    const int b = blockIdx.x, t = threadIdx.x;
    const int node = b * NPB + t;
    if (t < NPB && node < N_NODES) {
        g_rowptr[node] += g_boff[b];
        g_cnt[node] = 0;
    }
}

// ---------------------------------------------------------------------------
// CSR step 3: bucket edge sources by dst.
// ---------------------------------------------------------------------------
__global__ void fill_kernel(const void* __restrict__ ei, int E) {
    const int is64 = g_is64;
    for (int e = blockIdx.x * blockDim.x + threadIdx.x; e < E;
         e += gridDim.x * blockDim.x) {
        int s, d;
        if (is64) {
            s = (int)__ldg((const long long*)ei + e);
            d = (int)__ldg((const long long*)ei + E + e);
        } else {
            s = __ldg((const int*)ei + e);
            d = __ldg((const int*)ei + E + e);
        }
        int pos = g_rowptr[d] + atomicAdd(&g_cnt[d], 1);
        g_esrc[pos] = s;
    }
}

// ---------------------------------------------------------------------------
// Layer-1 mean gather: warp per node, lane = float4 chunk (24 active lanes).
// Shuffle-free, 8-way batched independent loads (explicit MLP>=8).
// ---------------------------------------------------------------------------
__global__ void gather1_kernel(const float* __restrict__ x) {
    const int node = blockIdx.x * (blockDim.x >> 5) + (threadIdx.x >> 5);
    if (node >= N_NODES) return;
    const int lane = threadIdx.x & 31;
    const bool act = lane < (F0 / 4);

    const int beg = __ldg(&g_rowptr[node]);
    const int end = __ldg(&g_rowptr[node + 1]);

    float4 a0 = {0,0,0,0}, a1 = {0,0,0,0}, a2 = {0,0,0,0}, a3 = {0,0,0,0};
    int j = beg;
    for (; j + 8 <= end; j += 8) {
        int s0 = __ldg(&g_esrc[j + 0]), s1 = __ldg(&g_esrc[j + 1]);
        int s2 = __ldg(&g_esrc[j + 2]), s3 = __ldg(&g_esrc[j + 3]);
        int s4 = __ldg(&g_esrc[j + 4]), s5 = __ldg(&g_esrc[j + 5]);
        int s6 = __ldg(&g_esrc[j + 6]), s7 = __ldg(&g_esrc[j + 7]);
        if (act) {
            float4 v0 = __ldg((const float4*)(x + (size_t)s0 * F0) + lane);
            float4 v1 = __ldg((const float4*)(x + (size_t)s1 * F0) + lane);
            float4 v2 = __ldg((const float4*)(x + (size_t)s2 * F0) + lane);
            float4 v3 = __ldg((const float4*)(x + (size_t)s3 * F0) + lane);
            float4 v4 = __ldg((const float4*)(x + (size_t)s4 * F0) + lane);
            float4 v5 = __ldg((const float4*)(x + (size_t)s5 * F0) + lane);
            float4 v6 = __ldg((const float4*)(x + (size_t)s6 * F0) + lane);
            float4 v7 = __ldg((const float4*)(x + (size_t)s7 * F0) + lane);
            a0.x += v0.x; a0.y += v0.y; a0.z += v0.z; a0.w += v0.w;
            a1.x += v1.x; a1.y += v1.y; a1.z += v1.z; a1.w += v1.w;
            a2.x += v2.x; a2.y += v2.y; a2.z += v2.z; a2.w += v2.w;
            a3.x += v3.x; a3.y += v3.y; a3.z += v3.z; a3.w += v3.w;
            a0.x += v4.x; a0.y += v4.y; a0.z += v4.z; a0.w += v4.w;
            a1.x += v5.x; a1.y += v5.y; a1.z += v5.z; a1.w += v5.w;
            a2.x += v6.x; a2.y += v6.y; a2.z += v6.z; a2.w += v6.w;
            a3.x += v7.x; a3.y += v7.y; a3.z += v7.z; a3.w += v7.w;
        }
    }
    for (; j < end; j++) {
        int s = __ldg(&g_esrc[j]);
        if (act) {
            float4 v = __ldg((const float4*)(x + (size_t)s * F0) + lane);
            a0.x += v.x; a0.y += v.y; a0.z += v.z; a0.w += v.w;
        }
    }
    if (act) {
        float inv = 1.0f / fmaxf((float)(end - beg), 1.0f);
        float4 r;
        r.x = (a0.x + a1.x + a2.x + a3.x) * inv;
        r.y = (a0.y + a1.y + a2.y + a3.y) * inv;
        r.z = (a0.z + a1.z + a2.z + a3.z) * inv;
        r.w = (a0.w + a1.w + a2.w + a3.w) * inv;
        *((float4*)(g_agg1 + (size_t)node * F0) + lane) = r;
    }
}

// ---------------------------------------------------------------------------
// FUSED layer-1 linear + layer-2 dual GEMM (h never touches global memory):
//   h  = relu(agg1 @ sgn(W1l)^T + b1 + x @ sgn(W1r)^T)      (in registers)
//   z  = h @ sgn(W2l)^T,  r = h @ sgn(W2r)^T                (smem round-trip)
// 64 threads, TN=16 nodes/block. Phase A: thread owns outputs {o, o+64},
// 2x FFMA2 reuse per LDS.128. Phase B: h staged as packed node-pair ulls
// (row stride 10 for 16B-aligned LDS.128 reads), thread owns one of 64
// outputs for BOTH W2 matrices.
// ---------------------------------------------------------------------------
__global__ void fused_gemm_kernel(const float* __restrict__ xin,
                                  const float* __restrict__ bias1) {
    const int TN = 16;
    const int PAIRS = TN / 2;                 // 8
    const int PSTRIDE = 10;                   // ull row stride (16B-aligned rows)
    __shared__ __align__(16) unsigned char smem_raw[2 * F0 * TN * 4];  // 12288 B
    float (*sa)[TN] = (float(*)[TN])smem_raw;
    float (*sx)[TN] = (float(*)[TN])(smem_raw + F0 * TN * 4);
    ull* shp = (ull*)smem_raw;                // reused after phase A (10240 B)

    const int node0 = blockIdx.x * TN;
    const int tid = threadIdx.x;              // 64
    const int Q = F0 / 4;                     // 24

    // ---- stage agg1/x transposed [F0][TN] ----
    for (int i = tid; i < TN * Q; i += 64) {
        int n = i & (TN - 1);
        int q = i >> 4;
        int node = node0 + n;
        float4 a  = __ldg((const float4*)(g_agg1 + (size_t)node * F0) + q);
        float4 xv = __ldg((const float4*)(xin    + (size_t)node * F0) + q);
        sa[4 * q + 0][n] = a.x;  sa[4 * q + 1][n] = a.y;
        sa[4 * q + 2][n] = a.z;  sa[4 * q + 3][n] = a.w;
        sx[4 * q + 0][n] = xv.x; sx[4 * q + 1][n] = xv.y;
        sx[4 * q + 2][n] = xv.z; sx[4 * q + 3][n] = xv.w;
    }
    __syncthreads();

    // ---- phase A: h for outputs o1=tid, o2=tid+64 ----
    const int o1 = tid, o2 = tid + 64;
    ull accA[PAIRS], accB[PAIRS];
    const ull bA = pack2dup(__ldg(&bias1[o1]));
    const ull bB = pack2dup(__ldg(&bias1[o2]));
    #pragma unroll
    for (int p = 0; p < PAIRS; p++) { accA[p] = bA; accB[p] = bB; }

    #pragma unroll 4
    for (int f = 0; f < F0; f++) {
        ull wlA = pack2dup(__ldg(&g_w1l[f * F1 + o1]));
        ull wlB = pack2dup(__ldg(&g_w1l[f * F1 + o2]));
        ull wrA = pack2dup(__ldg(&g_w1r[f * F1 + o1]));
        ull wrB = pack2dup(__ldg(&g_w1r[f * F1 + o2]));
        #pragma unroll
        for (int p = 0; p < PAIRS / 2; p++) {
            ulonglong2 va = *(const ulonglong2*)&sa[f][4 * p];
            ulonglong2 vx = *(const ulonglong2*)&sx[f][4 * p];
            fma2(accA[2 * p + 0], va.x, wlA);
            fma2(accA[2 * p + 1], va.y, wlA);
            fma2(accB[2 * p + 0], va.x, wlB);
            fma2(accB[2 * p + 1], va.y, wlB);
            fma2(accA[2 * p + 0], vx.x, wrA);
            fma2(accA[2 * p + 1], vx.y, wrA);
            fma2(accB[2 * p + 0], vx.x, wrB);
            fma2(accB[2 * p + 1], vx.y, wrB);
        }
    }
    __syncthreads();   // all sa/sx reads done; safe to overwrite smem

    // ---- phase B stage: relu(h) as node-pair ulls, rows [F1][PSTRIDE] ----
    #pragma unroll
    for (int p = 0; p < PAIRS; p++) {
        float2 hA = unpack2(accA[p]);
        float2 hB = unpack2(accB[p]);
        hA.x = fmaxf(hA.x, 0.f); hA.y = fmaxf(hA.y, 0.f);
        hB.x = fmaxf(hB.x, 0.f); hB.y = fmaxf(hB.y, 0.f);
        shp[o1 * PSTRIDE + p] = pack2(hA.x, hA.y);
        shp[o2 * PSTRIDE + p] = pack2(hB.x, hB.y);
    }
    __syncthreads();

    // ---- phase B: z = h@sgn(W2l)^T, r = h@sgn(W2r)^T; thread owns o=tid ----
    const int o = tid;                        // 64 outputs
    ull accz[PAIRS], accr[PAIRS];
    #pragma unroll
    for (int p = 0; p < PAIRS; p++) { accz[p] = 0ull; accr[p] = 0ull; }

    #pragma unroll 4
    for (int f = 0; f < F1; f++) {
        ull wz = pack2dup(__ldg(&g_w2l[f * F2 + o]));
        ull wr = pack2dup(__ldg(&g_w2r[f * F2 + o]));
        #pragma unroll
        for (int p = 0; p < PAIRS / 2; p++) {
            ulonglong2 v = *(const ulonglong2*)&shp[f * PSTRIDE + 2 * p];
            fma2(accz[2 * p + 0], v.x, wz);
            fma2(accz[2 * p + 1], v.y, wz);
            fma2(accr[2 * p + 0], v.x, wr);
            fma2(accr[2 * p + 1], v.y, wr);
        }
    }

    #pragma unroll
    for (int p = 0; p < PAIRS; p++) {
        float2 z = unpack2(accz[p]);
        float2 r = unpack2(accr[p]);
        g_z[(size_t)(node0 + 2 * p + 0) * F2 + o] = z.x;
        g_z[(size_t)(node0 + 2 * p + 1) * F2 + o] = z.y;
        g_r[(size_t)(node0 + 2 * p + 0) * F2 + o] = r.x;
        g_r[(size_t)(node0 + 2 * p + 1) * F2 + o] = r.y;
    }
}

// ---------------------------------------------------------------------------
// Layer-2 gather + epilogue: out[i] = mean_{j in N(i)} z[j] + b2 + r[i].
// Warp per node, lane = f32x2 chunk; 8-way batched independent loads.
// ---------------------------------------------------------------------------
__global__ void gather2_final_kernel(const float* __restrict__ b2,
                                     float* __restrict__ out) {
    const int node = blockIdx.x * (blockDim.x >> 5) + (threadIdx.x >> 5);
    if (node >= N_NODES) return;
    const int lane = threadIdx.x & 31;

    const int beg = __ldg(&g_rowptr[node]);
    const int end = __ldg(&g_rowptr[node + 1]);

    const ull* zb = (const ull*)g_z;      // row stride F2/2 = 32 ull
    ull a0 = 0, a1 = 0, a2 = 0, a3 = 0;
    int j = beg;
    for (; j + 8 <= end; j += 8) {
        int s0 = __ldg(&g_esrc[j + 0]), s1 = __ldg(&g_esrc[j + 1]);
        int s2 = __ldg(&g_esrc[j + 2]), s3 = __ldg(&g_esrc[j + 3]);
        int s4 = __ldg(&g_esrc[j + 4]), s5 = __ldg(&g_esrc[j + 5]);
        int s6 = __ldg(&g_esrc[j + 6]), s7 = __ldg(&g_esrc[j + 7]);
        ull v0 = __ldg(zb + (size_t)s0 * 32 + lane);
        ull v1 = __ldg(zb + (size_t)s1 * 32 + lane);
        ull v2 = __ldg(zb + (size_t)s2 * 32 + lane);
        ull v3 = __ldg(zb + (size_t)s3 * 32 + lane);
        ull v4 = __ldg(zb + (size_t)s4 * 32 + lane);
        ull v5 = __ldg(zb + (size_t)s5 * 32 + lane);
        ull v6 = __ldg(zb + (size_t)s6 * 32 + lane);
        ull v7 = __ldg(zb + (size_t)s7 * 32 + lane);
        add2(a0, v0); add2(a1, v1); add2(a2, v2); add2(a3, v3);
        add2(a0, v4); add2(a1, v5); add2(a2, v6); add2(a3, v7);
    }
    for (; j < end; j++) {
        int s = __ldg(&g_esrc[j]);
        add2(a0, __ldg(zb + (size_t)s * 32 + lane));
    }
    add2(a0, a1); add2(a2, a3); add2(a0, a2);

    float inv = 1.0f / fmaxf((float)(end - beg), 1.0f);
    float2 m = unpack2(a0);
    float2 bb = __ldg((const float2*)b2 + lane);
    float2 rr = __ldg((const float2*)g_r + (size_t)node * 32 + lane);
    float2 res;
    res.x = m.x * inv + bb.x + rr.x;
    res.y = m.y * inv + bb.y + rr.y;
    ((float2*)out)[(size_t)node * 32 + lane] = res;
}

// ---------------------------------------------------------------------------
// Launch sequence (graph-capturable: kernel launches only).
// ---------------------------------------------------------------------------
extern "C" void kernel_launch(void* const* d_in, const int* in_sizes, int n_in,
                              void* d_out, int out_size) {
    const float* x   = (const float*)d_in[0];
    const void*  ei  = d_in[1];
    const float* w1l = (const float*)d_in[2];
    const float* b1  = (const float*)d_in[3];
    const float* w1r = (const float*)d_in[4];
    const float* w2l = (const float*)d_in[5];
    const float* b2  = (const float*)d_in[6];
    const float* w2r = (const float*)d_in[7];
    float* out = (float*)d_out;

    const int E = in_sizes[1] / 2;        // 800000

    prep_kernel<<<128, 256>>>(ei, w1l, w1r, w2l, w2r);
    count_kernel<<<1024, 256>>>(ei, E);
    scanA_kernel<<<NB_SCAN, 256>>>();
    scanB_kernel<<<1, NB_SCAN>>>();
    scanC_kernel<<<NB_SCAN, 256>>>();
    fill_kernel<<<1024, 256>>>(ei, E);

    gather1_kernel<<<(N_NODES + 7) / 8, 256>>>(x);
    fused_gemm_kernel<<<N_NODES / 16, 64>>>(x, b1);
    gather2_final_kernel<<<(N_NODES + 7) / 8, 256>>>(b2, out);
}